// round 9
// baseline (speedup 1.0000x reference)
#include <cuda_runtime.h>

// Problem constants (fixed by setup_inputs):
// B=16, C=1, H=W=128, WS=8, N = B*WS*WS = 1024 windows, mask all ones.
// Canvas per batch: 1024 x 1024. Output = [canvas (16.7M f32) | windows copy (16.7M f32)].

#define NW        1024            // number of windows
#define BATCH     16
#define WSZ       8
#define CELLS     (WSZ * WSZ)     // 64 cells per batch
#define NTILES    (BATCH * CELLS) // 1024
#define HH        128
#define TILE_F4   (HH * HH / 4)   // 4096 float4 per tile
#define CANV_ROW4 (1024 / 4)      // 256 float4 per canvas row
#define CANV_B4   (1024 * 1024 / 4)

#define NSEG      8               // segments per tile (fine-grain balance)
#define SEG_F4    (TILE_F4 / NSEG)      // 512 float4 per segment
#define GTHREADS  128
#define JPT       (SEG_F4 / GTHREADS)   // 4 float4 per thread (MLP=4)

// ---------------------------------------------------------------------------
// Single fused kernel: grid (NTILES, NSEG) x 128 threads (8192 small blocks
// for tail-free scheduling; k-heavy tiles split into 8 independent pieces).
// Batch-local binning: tile fixes batch b = tile>>6; batch b's windows are
// the contiguous index range [csum[b-1], csum[b]) (searchsorted-right
// semantics), so each block scans <=64 windows. Then gather the k matching
// windows over this block's 512-float4 pixel segment with 4 independent
// streaming loads in flight per thread, fusing the verbatim windows copy
// (each window byte read exactly once chip-wide), and write the normalized
// canvas segment. All heavy traffic is read-once/write-once -> __ldcs/__stcs.
// ---------------------------------------------------------------------------
__global__ void __launch_bounds__(GTHREADS, 10) hre_fused_kernel(
    const float4* __restrict__ win4,      // windows as float4
    const int*    __restrict__ positions, // [NW,2]
    const int*    __restrict__ mask,      // [BATCH, CELLS]
    float4* __restrict__ canvas4,         // output canvas (first half)
    float4* __restrict__ copy4)           // output windows copy (second half)
{
    const int tile = blockIdx.x;
    const int seg  = blockIdx.y;
    const int tid  = threadIdx.x;

    const int b    = tile >> 6;           // batch of this tile
    const int cell = tile & 63;
    const int ty   = cell >> 3;
    const int tx   = cell & 7;

    __shared__ int bsum[BATCH];
    __shared__ int list_cnt;
    __shared__ int win_start, win_n;
    __shared__ unsigned short list[CELLS];

    // --- batch sizes: 128 threads x 8 mask entries = 1024 = BATCH*CELLS ----
    if (tid < BATCH) bsum[tid] = 0;
    if (tid == 0) list_cnt = 0;
    __syncthreads();
    {
        // thread t covers mask[t*8 .. t*8+8); all 8 lie in batch t>>3
        int part = 0;
        #pragma unroll
        for (int j = 0; j < 8; ++j) part += mask[tid * 8 + j];
        atomicAdd(&bsum[tid >> 3], part);
    }
    __syncthreads();
    if (tid == 0) {
        int s = 0, st = 0;
        #pragma unroll
        for (int bb = 0; bb < BATCH; ++bb) {
            if (bb == b) st = s;
            s += bsum[bb];
            if (bb == b) { win_start = st; win_n = s - st; }
        }
    }
    __syncthreads();

    // --- scan only this batch's window range (<= 64 windows) ---------------
    for (int i = win_start + tid; i < win_start + win_n; i += GTHREADS) {
        const int py = positions[2 * i + 0];
        const int px = positions[2 * i + 1];
        if (py == ty && px == tx) {
            const int s = atomicAdd(&list_cnt, 1);
            list[s] = (unsigned short)i;
        }
    }
    __syncthreads();
    const int k = list_cnt;

    // --- gather + fused copy ------------------------------------------------
    const int p0 = seg * SEG_F4 + tid;    // first float4 owned by this thread

    float4 acc[JPT];
    #pragma unroll
    for (int j = 0; j < JPT; ++j)
        acc[j] = make_float4(0.f, 0.f, 0.f, 0.f);

    for (int w = 0; w < k; ++w) {
        const int wi = list[w];
        const float4* __restrict__ src = win4  + (size_t)wi * TILE_F4 + p0;
        float4*       __restrict__ dst = copy4 + (size_t)wi * TILE_F4 + p0;

        float4 v[JPT];
        #pragma unroll
        for (int j = 0; j < JPT; ++j)     // 4 independent streaming loads
            v[j] = __ldcs(src + j * GTHREADS);
        #pragma unroll
        for (int j = 0; j < JPT; ++j) {
            __stcs(dst + j * GTHREADS, v[j]);   // fused windows passthrough
            acc[j].x += v[j].x; acc[j].y += v[j].y;
            acc[j].z += v[j].z; acc[j].w += v[j].w;
        }
    }

    // --- normalized canvas writes ------------------------------------------
    const float inv = 1.0f / ((float)k + 1e-6f);
    const int cbase = b * CANV_B4 + ty * HH * CANV_ROW4 + tx * (HH / 4);

    #pragma unroll
    for (int j = 0; j < JPT; ++j) {
        const int p4 = p0 + j * GTHREADS;       // 0..4095 within tile
        const int r  = p4 >> 5;                 // 32 f4 per tile row
        const int c4 = p4 & 31;
        __stcs(canvas4 + cbase + r * CANV_ROW4 + c4,
               make_float4(acc[j].x * inv, acc[j].y * inv,
                           acc[j].z * inv, acc[j].w * inv));
    }
}

// ---------------------------------------------------------------------------
extern "C" void kernel_launch(void* const* d_in, const int* in_sizes, int n_in,
                              void* d_out, int out_size)
{
    const float* windows   = (const float*)d_in[0];   // [NW,1,128,128] f32
    const int*   positions = (const int*)  d_in[1];   // [NW,2] i32
    const int*   mask      = (const int*)  d_in[2];   // [16,64] i32
    (void)in_sizes; (void)n_in; (void)out_size;

    float* out = (float*)d_out;
    float4* canvas4 = (float4*)out;
    float4* copy4   = (float4*)(out + (size_t)BATCH * 1024 * 1024);

    dim3 grid(NTILES, NSEG);
    hre_fused_kernel<<<grid, GTHREADS>>>((const float4*)windows, positions, mask,
                                         canvas4, copy4);
}

// round 10
// speedup vs baseline: 1.0796x; 1.0796x over previous
#include <cuda_runtime.h>

// Problem constants (fixed by setup_inputs):
// B=16, C=1, H=W=128, WS=8, N = B*WS*WS = 1024 windows, mask all ones.
// Canvas per batch: 1024 x 1024. Output = [canvas (16.7M f32) | windows copy (16.7M f32)].

#define NW        1024            // number of windows
#define BATCH     16
#define WSZ       8
#define CELLS     (WSZ * WSZ)     // 64 cells per batch
#define NTILES    (BATCH * CELLS) // 1024
#define HH        128
#define TILE_F4   (HH * HH / 4)   // 4096 float4 per tile
#define CANV_ROW4 (1024 / 4)      // 256 float4 per canvas row
#define CANV_B4   (1024 * 1024 / 4)

#define NSEG      4               // segments per tile
#define SEG_F4    (TILE_F4 / NSEG)      // 1024 float4 per segment
#define GTHREADS  256
#define JPT       (SEG_F4 / GTHREADS)   // 4 float4 per thread

// ---------------------------------------------------------------------------
// Single fused kernel: grid (NSEG, NTILES) x 256 threads.
// SEG-MAJOR ordering: blockIdx.x = segment, blockIdx.y = tile, so the 4
// consecutively-scheduled CTAs of one tile sweep each source window's 16 KB
// and the destination canvas tile contiguously -> better DRAM row locality
// for all three streams.
// Batch-local binning: tile fixes batch b = tile>>6; batch b's windows are
// the contiguous index range [csum[b-1], csum[b]) (searchsorted-right
// semantics), so each block scans <=64 windows. Then gather the k matching
// windows over this block's 1024-float4 segment with 4 independent streaming
// loads in flight per thread, fusing the verbatim windows copy (each window
// byte read exactly once chip-wide), and write the normalized canvas segment.
// Loads are read-once -> __ldcs; stores use default write-back so L2 absorbs
// write bursts.
// ---------------------------------------------------------------------------
__global__ void __launch_bounds__(GTHREADS) hre_fused_kernel(
    const float4* __restrict__ win4,      // windows as float4
    const int*    __restrict__ positions, // [NW,2]
    const int*    __restrict__ mask,      // [BATCH, CELLS]
    float4* __restrict__ canvas4,         // output canvas (first half)
    float4* __restrict__ copy4)           // output windows copy (second half)
{
    const int seg  = blockIdx.x;          // seg-major: consecutive bids share a tile
    const int tile = blockIdx.y;
    const int tid  = threadIdx.x;

    const int b    = tile >> 6;           // batch of this tile
    const int cell = tile & 63;
    const int ty   = cell >> 3;
    const int tx   = cell & 7;

    __shared__ int bsum[BATCH];
    __shared__ int list_cnt;
    __shared__ int win_start, win_n;
    __shared__ unsigned short list[CELLS];

    // --- batch sizes: 256 threads x 4 mask entries = 1024 = BATCH*CELLS ----
    if (tid < BATCH) bsum[tid] = 0;
    if (tid == 0) list_cnt = 0;
    __syncthreads();
    {
        // thread t covers mask[t*4 .. t*4+4); all 4 lie in batch t>>4
        int part = 0;
        #pragma unroll
        for (int j = 0; j < 4; ++j) part += mask[tid * 4 + j];
        atomicAdd(&bsum[tid >> 4], part);
    }
    __syncthreads();
    if (tid == 0) {
        int s = 0, st = 0;
        #pragma unroll
        for (int bb = 0; bb < BATCH; ++bb) {
            if (bb == b) st = s;
            s += bsum[bb];
            if (bb == b) { win_start = st; win_n = s - st; }
        }
    }
    __syncthreads();

    // --- scan only this batch's window range (<= 64 windows) ---------------
    for (int i = win_start + tid; i < win_start + win_n; i += GTHREADS) {
        const int py = positions[2 * i + 0];
        const int px = positions[2 * i + 1];
        if (py == ty && px == tx) {
            const int s = atomicAdd(&list_cnt, 1);
            list[s] = (unsigned short)i;
        }
    }
    __syncthreads();
    const int k = list_cnt;

    // --- gather + fused copy ------------------------------------------------
    const int p0 = seg * SEG_F4 + tid;    // first float4 owned by this thread

    float4 acc[JPT];
    #pragma unroll
    for (int j = 0; j < JPT; ++j)
        acc[j] = make_float4(0.f, 0.f, 0.f, 0.f);

    for (int w = 0; w < k; ++w) {
        const int wi = list[w];
        const float4* __restrict__ src = win4  + (size_t)wi * TILE_F4 + p0;
        float4*       __restrict__ dst = copy4 + (size_t)wi * TILE_F4 + p0;

        float4 v[JPT];
        #pragma unroll
        for (int j = 0; j < JPT; ++j)     // 4 independent streaming loads
            v[j] = __ldcs(src + j * GTHREADS);
        #pragma unroll
        for (int j = 0; j < JPT; ++j) {
            dst[j * GTHREADS] = v[j];     // fused windows passthrough (write-back)
            acc[j].x += v[j].x; acc[j].y += v[j].y;
            acc[j].z += v[j].z; acc[j].w += v[j].w;
        }
    }

    // --- normalized canvas writes ------------------------------------------
    const float inv = 1.0f / ((float)k + 1e-6f);
    const int cbase = b * CANV_B4 + ty * HH * CANV_ROW4 + tx * (HH / 4);

    #pragma unroll
    for (int j = 0; j < JPT; ++j) {
        const int p4 = p0 + j * GTHREADS;       // 0..4095 within tile
        const int r  = p4 >> 5;                 // 32 f4 per tile row
        const int c4 = p4 & 31;
        canvas4[cbase + r * CANV_ROW4 + c4] =
            make_float4(acc[j].x * inv, acc[j].y * inv,
                        acc[j].z * inv, acc[j].w * inv);
    }
}

// ---------------------------------------------------------------------------
extern "C" void kernel_launch(void* const* d_in, const int* in_sizes, int n_in,
                              void* d_out, int out_size)
{
    const float* windows   = (const float*)d_in[0];   // [NW,1,128,128] f32
    const int*   positions = (const int*)  d_in[1];   // [NW,2] i32
    const int*   mask      = (const int*)  d_in[2];   // [16,64] i32
    (void)in_sizes; (void)n_in; (void)out_size;

    float* out = (float*)d_out;
    float4* canvas4 = (float4*)out;
    float4* copy4   = (float4*)(out + (size_t)BATCH * 1024 * 1024);

    dim3 grid(NSEG, NTILES);              // seg-major
    hre_fused_kernel<<<grid, GTHREADS>>>((const float4*)windows, positions, mask,
                                         canvas4, copy4);
}